// round 9
// baseline (speedup 1.0000x reference)
#include <cuda_runtime.h>
#include <cuda_bf16.h>
#include <cstdint>
#include <math.h>

#define CC   512
#define HWN  6400
#define EPS5 1e-5f

// ---------------- device scratch (no runtime allocation allowed) ----------------
__device__ float g_ymu [CC];
__device__ float g_ssx [HWN];   // per-pixel sum of squares (x)
__device__ float g_ssy [HWN];
__device__ float g_max_ [2 * HWN];  // per-pixel maxabs (x then y)
__device__ float g_fx  [HWN];   // dequant factor x: ma/(127*norm)
__device__ float g_fy  [HWN];
__device__ int8_t g_xq[HWN * CC];                  // quantized xn [i][c]
__device__ int8_t g_yq[HWN * CC];                  // quantized yn [j][c]
__device__ __nv_bfloat16 g_Ab[(size_t)HWN * HWN];  // 6400x6400 bf16 Gram (81.92 MB)
__device__ float g_rowmax[HWN];
__device__ float g_k   [HWN];

// ---------------- helpers ----------------
__device__ __forceinline__ uint32_t smem_to_u32(const void* smem_ptr) {
    uint32_t addr;
    asm("{ .reg .u64 tmp; cvta.to.shared.u64 tmp, %1; cvt.u32.u64 %0, tmp; }"
        : "=r"(addr) : "l"(smem_ptr));
    return addr;
}
__device__ __forceinline__ void cp_async16(uint32_t dst, const void* src) {
    asm volatile("cp.async.cg.shared.global [%0], [%1], 16;" :: "r"(dst), "l"(src) : "memory");
}
__device__ __forceinline__ void cp_commit() {
    asm volatile("cp.async.commit_group;" ::: "memory");
}
template<int N>
__device__ __forceinline__ void cp_wait() {
    asm volatile("cp.async.wait_group %0;" :: "n"(N) : "memory");
}
__device__ __forceinline__ void ldmatrix_x4(uint32_t* r, uint32_t addr) {
    asm volatile("ldmatrix.sync.aligned.m8n8.x4.shared.b16 {%0,%1,%2,%3}, [%4];"
        : "=r"(r[0]), "=r"(r[1]), "=r"(r[2]), "=r"(r[3]) : "r"(addr));
}
// int8 IMMA: m16n8k32, s32 accumulate. Fragments byte-identical to bf16 m16n8k16.
__device__ __forceinline__ void mma_s8(int* c, const uint32_t* a,
                                       uint32_t b0, uint32_t b1) {
    asm volatile(
        "mma.sync.aligned.m16n8k32.row.col.s32.s8.s8.s32 "
        "{%0,%1,%2,%3}, {%4,%5,%6,%7}, {%8,%9}, {%0,%1,%2,%3};"
        : "+r"(c[0]), "+r"(c[1]), "+r"(c[2]), "+r"(c[3])
        : "r"(a[0]), "r"(a[1]), "r"(a[2]), "r"(a[3]), "r"(b0), "r"(b1));
}
__device__ __forceinline__ void atomicMaxFloat(float* addr, float v) {
    if (v >= 0.0f) atomicMax((int*)addr, __float_as_int(v));
    else           atomicMin((unsigned int*)addr, __float_as_uint(v));
}

// ---------------- reductions ----------------
__device__ __forceinline__ float warpReduceSum(float v) {
#pragma unroll
    for (int o = 16; o > 0; o >>= 1) v += __shfl_xor_sync(0xffffffffu, v, o);
    return v;
}
__device__ __forceinline__ float warpReduceMax(float v) {
#pragma unroll
    for (int o = 16; o > 0; o >>= 1) v = fmaxf(v, __shfl_xor_sync(0xffffffffu, v, o));
    return v;
}
__device__ __forceinline__ float blockReduceSum(float v) {
    __shared__ float sh[8];
    int lane = threadIdx.x & 31, w = threadIdx.x >> 5;
    v = warpReduceSum(v);
    if (lane == 0) sh[w] = v;
    __syncthreads();
    v = (threadIdx.x < 8) ? sh[threadIdx.x] : 0.0f;
    if (w == 0) v = warpReduceSum(v);
    __syncthreads();
    return v;
}
__device__ __forceinline__ float blockReduceMax(float v) {
    __shared__ float sh[8];
    int lane = threadIdx.x & 31, w = threadIdx.x >> 5;
    v = warpReduceMax(v);
    if (lane == 0) sh[w] = v;
    __syncthreads();
    v = (threadIdx.x < 8) ? sh[threadIdx.x] : -3.0e38f;
    if (w == 0) v = warpReduceMax(v);
    __syncthreads();
    return v;
}

// ---------------- stage 0: init ----------------
__global__ void init_kernel() {
    const int i = blockIdx.x * 256 + threadIdx.x;
    g_rowmax[i] = -3.0e38f;
    g_ssx[i] = 0.0f;
    g_ssy[i] = 0.0f;
    g_max_[i] = 0.0f;
    g_max_[HWN + i] = 0.0f;
}

// ---------------- stage 1: per-channel mean of y ----------------
__global__ void ymu_kernel(const float* __restrict__ y) {
    const int c = blockIdx.x;
    const float4* row = reinterpret_cast<const float4*>(y + (size_t)c * HWN);
    float s = 0.0f;
    for (int j = threadIdx.x; j < HWN / 4; j += blockDim.x) {
        float4 v = row[j];
        s += (v.x + v.y) + (v.z + v.w);
    }
    s = blockReduceSum(s);
    if (threadIdx.x == 0) g_ymu[c] = s * (1.0f / HWN);
}

// ---------------- stage 2: per-pixel partial sumsq + maxabs (32-ch slabs) ----------------
__global__ void sumsq_kernel(const float* __restrict__ v, float* __restrict__ ss,
                             float* __restrict__ ma) {
    __shared__ float smu[32];
    const int c0 = blockIdx.y * 32;
    if (threadIdx.x < 32) smu[threadIdx.x] = g_ymu[c0 + threadIdx.x];
    __syncthreads();
    const int i = blockIdx.x * 256 + threadIdx.x;
    float s = 0.0f, m = 0.0f;
#pragma unroll 8
    for (int c = 0; c < 32; c++) {
        float t = v[(size_t)(c0 + c) * HWN + i] - smu[c];
        s = fmaf(t, t, s);
        m = fmaxf(m, fabsf(t));
    }
    atomicAdd(&ss[i], s);
    atomicMaxFloat(&ma[i], m);
}

// ---------------- stage 3: center+quantize+transpose to int8 [i][c] ----------------
__global__ void transpose_kernel(const float* __restrict__ v, const float* __restrict__ ss,
                                 const float* __restrict__ ma,
                                 int8_t* __restrict__ o, float* __restrict__ f) {
    __shared__ float tile[32][33];
    __shared__ float mu[32], qs[32];
    const int i0 = blockIdx.x * 32;
    const int c0 = blockIdx.y * 32;
    const int tx = threadIdx.x, ty = threadIdx.y;   // (32, 8)
    if (ty == 0) {
        mu[tx] = g_ymu[c0 + tx];
        float m = fmaxf(ma[i0 + tx], 1e-20f);
        qs[tx] = 127.0f / m;
        if (blockIdx.y == 0)
            f[i0 + tx] = m / (127.0f * fmaxf(sqrtf(ss[i0 + tx]), 1e-12f));
    }
    __syncthreads();
#pragma unroll
    for (int r = 0; r < 4; r++) {
        int cl = ty + 8 * r;
        tile[cl][tx] = (v[(size_t)(c0 + cl) * HWN + i0 + tx] - mu[cl]) * qs[tx];
    }
    __syncthreads();
#pragma unroll
    for (int r = 0; r < 4; r++) {
        int il = ty + 8 * r;
        int q = __float2int_rn(tile[tx][il]);
        o[(size_t)(i0 + il) * CC + c0 + tx] = (int8_t)q;
    }
}

// ---------------- stage 4: int8 IMMA GEMM A = f_i f_j (Xq * Yq^T) ----------------
// CTA tile 128x128, 8 warps 2(m) x 4(n), warp tile 64x32, BK=64 int8,
// 3-stage cp.async pipeline, rows padded to 80 B. Byte layout identical to
// the bf16 version (64 B data rows), so ldmatrix/mma indexing is unchanged.
#define BM 128
#define BN 128
#define BK 64
#define ROWB 80
#define NKC (CC / BK)    // 8 k-chunks
#define STG 3
#define ABYTES (BM * ROWB)
#define BBYTES (BN * ROWB)
#define GEMM_SMEM (STG * (ABYTES + BBYTES) + 512)

__global__ void __launch_bounds__(256, 2) gemm_mma(const int8_t* __restrict__ X,
                                                   const int8_t* __restrict__ Y,
                                                   __nv_bfloat16* __restrict__ A) {
    extern __shared__ __align__(16) char dyn[];
    char* sAp = dyn;
    char* sBp = dyn + STG * ABYTES;
    float* sRM = reinterpret_cast<float*>(dyn + STG * (ABYTES + BBYTES));

    const int tid  = threadIdx.x;
    const int wid  = tid >> 5;
    const int lane = tid & 31;
    const int wm   = wid & 1;
    const int wn   = wid >> 1;
    const int i0   = blockIdx.y * BM;
    const int j0   = blockIdx.x * BN;

    if (tid < BM) sRM[tid] = -3.0e38f;

    const uint32_t aBase = smem_to_u32(sAp);
    const uint32_t bBase = smem_to_u32(sBp);

    // 128 rows x 64B = 512 16B segments per matrix per chunk, 2 per thread
    const int r0 = tid >> 2,         s0 = tid & 3;
    const int r1 = (tid + 256) >> 2, s1 = (tid + 256) & 3;
    const int8_t* Xg = X + (size_t)i0 * CC;
    const int8_t* Yg = Y + (size_t)j0 * CC;

    auto issue_chunk = [&](int kc, int buf) {
        const uint32_t da = aBase + buf * ABYTES;
        const uint32_t db = bBase + buf * BBYTES;
        const int ko = kc * BK;
        cp_async16(da + r0 * ROWB + s0 * 16, Xg + (size_t)r0 * CC + ko + s0 * 16);
        cp_async16(da + r1 * ROWB + s1 * 16, Xg + (size_t)r1 * CC + ko + s1 * 16);
        cp_async16(db + r0 * ROWB + s0 * 16, Yg + (size_t)r0 * CC + ko + s0 * 16);
        cp_async16(db + r1 * ROWB + s1 * 16, Yg + (size_t)r1 * CC + ko + s1 * 16);
        cp_commit();
    };

    int acc[4][4][4];
#pragma unroll
    for (int mt = 0; mt < 4; mt++)
#pragma unroll
        for (int nt = 0; nt < 4; nt++)
#pragma unroll
            for (int q = 0; q < 4; q++) acc[mt][nt][q] = 0;

    issue_chunk(0, 0);
    issue_chunk(1, 1);

    const int aRow = wm * 64 + (lane & 15);
    const uint32_t aColHalf = ((lane >> 4) & 1) * 16;
    const int bRow = wn * 32 + (lane & 7) + ((lane >> 4) & 1) * 8;
    const uint32_t bColHalf = ((lane >> 3) & 1) * 16;

    for (int kc = 0; kc < NKC; kc++) {
        const int buf = kc % STG;
        if (kc + 2 < NKC) { issue_chunk(kc + 2, (kc + 2) % STG); cp_wait<2>(); }
        else if (kc + 1 < NKC) { cp_wait<1>(); }
        else { cp_wait<0>(); }
        __syncthreads();

        const uint32_t ab = aBase + buf * ABYTES;
        const uint32_t bb = bBase + buf * BBYTES;
#pragma unroll
        for (int ks = 0; ks < 2; ks++) {
            uint32_t afr[4][4];
#pragma unroll
            for (int mt = 0; mt < 4; mt++)
                ldmatrix_x4(afr[mt], ab + (uint32_t)(aRow + mt * 16) * ROWB + ks * 32 + aColHalf);
            uint32_t bfr[2][4];
#pragma unroll
            for (int pr = 0; pr < 2; pr++)
                ldmatrix_x4(bfr[pr], bb + (uint32_t)(bRow + pr * 16) * ROWB + ks * 32 + bColHalf);
#pragma unroll
            for (int mt = 0; mt < 4; mt++)
#pragma unroll
                for (int nt = 0; nt < 4; nt++)
                    mma_s8(acc[mt][nt], afr[mt],
                           bfr[nt >> 1][(nt & 1) * 2], bfr[nt >> 1][(nt & 1) * 2 + 1]);
        }
        __syncthreads();
    }

    // ---------------- epilogue: dequant + bf16 store + fused row-max ----------------
    const int nb = j0 + wn * 32 + 2 * (lane & 3);
    float fy0[4], fy1[4];
#pragma unroll
    for (int nt = 0; nt < 4; nt++) {
        fy0[nt] = g_fy[nb + nt * 8];
        fy1[nt] = g_fy[nb + nt * 8 + 1];
    }
#pragma unroll
    for (int mt = 0; mt < 4; mt++) {
        const int mlo = i0 + wm * 64 + mt * 16 + (lane >> 2);
        const float fxlo = g_fx[mlo];
        const float fxhi = g_fx[mlo + 8];
        float maxlo = -3.0e38f, maxhi = -3.0e38f;
#pragma unroll
        for (int nt = 0; nt < 4; nt++) {
            float c0 = (float)acc[mt][nt][0] * fxlo * fy0[nt];
            float c1 = (float)acc[mt][nt][1] * fxlo * fy1[nt];
            float c2 = (float)acc[mt][nt][2] * fxhi * fy0[nt];
            float c3 = (float)acc[mt][nt][3] * fxhi * fy1[nt];
            maxlo = fmaxf(maxlo, fmaxf(c0, c1));
            maxhi = fmaxf(maxhi, fmaxf(c2, c3));
            __nv_bfloat162 lo = __floats2bfloat162_rn(c0, c1);
            __nv_bfloat162 hi = __floats2bfloat162_rn(c2, c3);
            *reinterpret_cast<__nv_bfloat162*>(A + (size_t)mlo * HWN + nb + nt * 8)       = lo;
            *reinterpret_cast<__nv_bfloat162*>(A + (size_t)(mlo + 8) * HWN + nb + nt * 8) = hi;
        }
        maxlo = fmaxf(maxlo, __shfl_xor_sync(0xffffffffu, maxlo, 1));
        maxlo = fmaxf(maxlo, __shfl_xor_sync(0xffffffffu, maxlo, 2));
        maxhi = fmaxf(maxhi, __shfl_xor_sync(0xffffffffu, maxhi, 1));
        maxhi = fmaxf(maxhi, __shfl_xor_sync(0xffffffffu, maxhi, 2));
        if ((lane & 3) == 0) {
            int rl = wm * 64 + mt * 16 + (lane >> 2);
            atomicMaxFloat(&sRM[rl],     maxlo);
            atomicMaxFloat(&sRM[rl + 8], maxhi);
        }
    }
    __syncthreads();
    if (tid < BM) atomicMaxFloat(&g_rowmax[i0 + tid], sRM[tid]);
}

// ---------------- stage 5: per-row exp pass -> k[i] ----------------
// cx_sp == I (spatial branch collapses to identity in fp32; see R2 analysis)
__global__ void cx_row_kernel(const __nv_bfloat16* __restrict__ A) {
    const int row = blockIdx.x;
    const float beta  = 2.0f / (1.0f - g_rowmax[row] + EPS5);
    const float alpha = 2.0f - beta;
    const uint4* Ar = reinterpret_cast<const uint4*>(A + (size_t)row * HWN);
    float s = 0.0f, m = 0.0f;
    for (int q = threadIdx.x; q < HWN / 8; q += blockDim.x) {
        uint4 u = Ar[q];
        const __nv_bfloat162* p = reinterpret_cast<const __nv_bfloat162*>(&u);
#pragma unroll
        for (int t = 0; t < 4; t++) {
            float2 f = __bfloat1622float2(p[t]);
            float w0 = __expf(fmaf(beta, f.x, alpha));
            float w1 = __expf(fmaf(beta, f.y, alpha));
            s += w0 + w1;
            m = fmaxf(m, fmaxf(w0, w1));
        }
    }
    s = blockReduceSum(s);
    m = blockReduceMax(m);
    if (threadIdx.x == 0) {
        float aii = __bfloat162float(A[(size_t)row * HWN + row]);
        float wii = __expf(fmaf(beta, aii, alpha));
        float inv_s = 1.0f / s;
        g_k[row] = fmaxf(0.9f * m * inv_s, fmaf(0.9f * wii, inv_s, 0.1f));
    }
}

// ---------------- stage 6: scalar output ----------------
__global__ void final_kernel(float* __restrict__ out) {
    float s = 0.0f;
    for (int i = threadIdx.x; i < HWN; i += blockDim.x) s += g_k[i];
    s = blockReduceSum(s);
    if (threadIdx.x == 0) out[0] = -logf(s * (1.0f / HWN) + EPS5);
}

// ---------------- launch ----------------
extern "C" void kernel_launch(void* const* d_in, const int* in_sizes, int n_in,
                              void* d_out, int out_size) {
    const float* x = (const float*)d_in[0];
    const float* y = (const float*)d_in[1];
    float* out = (float*)d_out;

    int8_t *pxq, *pyq;
    __nv_bfloat16 *pAb;
    float *pssx, *pssy, *pma, *pfx, *pfy;
    cudaGetSymbolAddress((void**)&pxq,  g_xq);
    cudaGetSymbolAddress((void**)&pyq,  g_yq);
    cudaGetSymbolAddress((void**)&pAb,  g_Ab);
    cudaGetSymbolAddress((void**)&pssx, g_ssx);
    cudaGetSymbolAddress((void**)&pssy, g_ssy);
    cudaGetSymbolAddress((void**)&pma,  g_max_);
    cudaGetSymbolAddress((void**)&pfx,  g_fx);
    cudaGetSymbolAddress((void**)&pfy,  g_fy);

    static bool attr_set = false;
    if (!attr_set) {
        cudaFuncSetAttribute(gemm_mma, cudaFuncAttributeMaxDynamicSharedMemorySize, GEMM_SMEM);
        attr_set = true;
    }

    init_kernel<<<HWN / 256, 256>>>();
    ymu_kernel<<<CC, 256>>>(y);
    sumsq_kernel<<<dim3(HWN / 256, CC / 32), 256>>>(x, pssx, pma);
    sumsq_kernel<<<dim3(HWN / 256, CC / 32), 256>>>(y, pssy, pma + HWN);
    transpose_kernel<<<dim3(HWN / 32, CC / 32), dim3(32, 8)>>>(x, pssx, pma, pxq, pfx);
    transpose_kernel<<<dim3(HWN / 32, CC / 32), dim3(32, 8)>>>(y, pssy, pma + HWN, pyq, pfy);
    gemm_mma<<<dim3(HWN / BN, HWN / BM), 256, GEMM_SMEM>>>(pxq, pyq, pAb);
    cx_row_kernel<<<HWN, 256>>>(pAb);
    final_kernel<<<1, 256>>>(out);
}

// round 10
// speedup vs baseline: 1.5006x; 1.5006x over previous
#include <cuda_runtime.h>
#include <cuda_bf16.h>
#include <cstdint>
#include <math.h>

#define CC   512
#define HWN  6400
#define EPS5 1e-5f

// ---------------- device scratch (no runtime allocation allowed) ----------------
__device__ float g_ymu [CC];
__device__ float g_ssx [HWN];                      // per-pixel sum of squares (x)
__device__ float g_ssy [HWN];
__device__ __nv_bfloat16 g_xb[HWN * CC];           // xn transposed [i][c], bf16
__device__ __nv_bfloat16 g_yb[HWN * CC];           // yn transposed [j][c], bf16
__device__ __nv_bfloat16 g_Ab[(size_t)HWN * HWN];  // 6400x6400 bf16 Gram (81.92 MB)
__device__ float g_rowmax[HWN];
__device__ float g_k   [HWN];

// ---------------- helpers ----------------
__device__ __forceinline__ uint32_t smem_to_u32(const void* smem_ptr) {
    uint32_t addr;
    asm("{ .reg .u64 tmp; cvta.to.shared.u64 tmp, %1; cvt.u32.u64 %0, tmp; }"
        : "=r"(addr) : "l"(smem_ptr));
    return addr;
}
__device__ __forceinline__ void cp_async16(uint32_t dst, const void* src) {
    asm volatile("cp.async.cg.shared.global [%0], [%1], 16;" :: "r"(dst), "l"(src) : "memory");
}
__device__ __forceinline__ void cp_commit() {
    asm volatile("cp.async.commit_group;" ::: "memory");
}
template<int N>
__device__ __forceinline__ void cp_wait() {
    asm volatile("cp.async.wait_group %0;" :: "n"(N) : "memory");
}
__device__ __forceinline__ void ldmatrix_x4(uint32_t* r, uint32_t addr) {
    asm volatile("ldmatrix.sync.aligned.m8n8.x4.shared.b16 {%0,%1,%2,%3}, [%4];"
        : "=r"(r[0]), "=r"(r[1]), "=r"(r[2]), "=r"(r[3]) : "r"(addr));
}
__device__ __forceinline__ void mma_16816(float* c, const uint32_t* a,
                                          uint32_t b0, uint32_t b1) {
    asm volatile(
        "mma.sync.aligned.m16n8k16.row.col.f32.bf16.bf16.f32 "
        "{%0,%1,%2,%3}, {%4,%5,%6,%7}, {%8,%9}, {%0,%1,%2,%3};"
        : "+f"(c[0]), "+f"(c[1]), "+f"(c[2]), "+f"(c[3])
        : "r"(a[0]), "r"(a[1]), "r"(a[2]), "r"(a[3]), "r"(b0), "r"(b1));
}
__device__ __forceinline__ void atomicMaxFloat(float* addr, float v) {
    if (v >= 0.0f) atomicMax((int*)addr, __float_as_int(v));
    else           atomicMin((unsigned int*)addr, __float_as_uint(v));
}

// ---------------- reductions ----------------
__device__ __forceinline__ float warpReduceSum(float v) {
#pragma unroll
    for (int o = 16; o > 0; o >>= 1) v += __shfl_xor_sync(0xffffffffu, v, o);
    return v;
}
__device__ __forceinline__ float warpReduceMax(float v) {
#pragma unroll
    for (int o = 16; o > 0; o >>= 1) v = fmaxf(v, __shfl_xor_sync(0xffffffffu, v, o));
    return v;
}
__device__ __forceinline__ float blockReduceSum(float v) {
    __shared__ float sh[8];
    int lane = threadIdx.x & 31, w = threadIdx.x >> 5;
    v = warpReduceSum(v);
    if (lane == 0) sh[w] = v;
    __syncthreads();
    v = (threadIdx.x < 8) ? sh[threadIdx.x] : 0.0f;
    if (w == 0) v = warpReduceSum(v);
    __syncthreads();
    return v;
}
__device__ __forceinline__ float blockReduceMax(float v) {
    __shared__ float sh[8];
    int lane = threadIdx.x & 31, w = threadIdx.x >> 5;
    v = warpReduceMax(v);
    if (lane == 0) sh[w] = v;
    __syncthreads();
    v = (threadIdx.x < 8) ? sh[threadIdx.x] : -3.0e38f;
    if (w == 0) v = warpReduceMax(v);
    __syncthreads();
    return v;
}

// ---------------- stage 0: init (rowmax = -inf, ss = 0) ----------------
__global__ void init_kernel() {
    const int i = blockIdx.x * 256 + threadIdx.x;
    g_rowmax[i] = -3.0e38f;
    g_ssx[i] = 0.0f;
    g_ssy[i] = 0.0f;
}

// ---------------- stage 1: per-channel mean of y ----------------
__global__ void ymu_kernel(const float* __restrict__ y) {
    const int c = blockIdx.x;
    const float4* row = reinterpret_cast<const float4*>(y + (size_t)c * HWN);
    float s = 0.0f;
    for (int j = threadIdx.x; j < HWN / 4; j += blockDim.x) {
        float4 v = row[j];
        s += (v.x + v.y) + (v.z + v.w);
    }
    s = blockReduceSum(s);
    if (threadIdx.x == 0) g_ymu[c] = s * (1.0f / HWN);
}

// ---------------- stage 2: per-pixel partial sum of squares (16-ch slabs) ----------------
// grid (HWN/256, CC/16): more CTAs -> latency hiding; atomicAdd merges slabs.
__global__ void sumsq_kernel(const float* __restrict__ v, float* __restrict__ ss) {
    __shared__ float smu[16];
    const int c0 = blockIdx.y * 16;
    if (threadIdx.x < 16) smu[threadIdx.x] = g_ymu[c0 + threadIdx.x];
    __syncthreads();
    const int i = blockIdx.x * 256 + threadIdx.x;
    float s = 0.0f;
#pragma unroll
    for (int c = 0; c < 16; c++) {
        float t = v[(size_t)(c0 + c) * HWN + i] - smu[c];
        s = fmaf(t, t, s);
    }
    atomicAdd(&ss[i], s);
}

// ---------------- stage 3: center+scale+transpose to bf16 [i][c] ----------------
__global__ void transpose_kernel(const float* __restrict__ v, const float* __restrict__ ss,
                                 __nv_bfloat16* __restrict__ o) {
    __shared__ float tile[32][33];
    __shared__ float mu[32], sinv[32];
    const int i0 = blockIdx.x * 32;
    const int c0 = blockIdx.y * 32;
    const int tx = threadIdx.x, ty = threadIdx.y;   // (32, 8)
    if (ty == 0) {
        mu[tx] = g_ymu[c0 + tx];
        sinv[tx] = 1.0f / fmaxf(sqrtf(ss[i0 + tx]), 1e-12f);
    }
    __syncthreads();
#pragma unroll
    for (int r = 0; r < 4; r++) {
        int cl = ty + 8 * r;
        tile[cl][tx] = (v[(size_t)(c0 + cl) * HWN + i0 + tx] - mu[cl]) * sinv[tx];
    }
    __syncthreads();
#pragma unroll
    for (int r = 0; r < 4; r++) {
        int il = ty + 8 * r;
        o[(size_t)(i0 + il) * CC + c0 + tx] = __float2bfloat16(tile[tx][il]);
    }
}

// ---------------- stage 4: bf16 warp-MMA GEMM A = Xb * Yb^T ----------------
// CTA tile 128(M) x 256(N), 8 warps 2(m) x 4(n), warp tile 64x64, BK=32,
// 3-stage cp.async pipeline, rows padded to 80 B. 1 CTA/SM.
#define BM 128
#define BN 256
#define BK 32
#define ROWB 80          // 32 bf16 = 64B data + 16B pad
#define NKC (CC / BK)    // 16 k-chunks
#define STG 3
#define ABYTES (BM * ROWB)
#define BBYTES (BN * ROWB)
#define GEMM_SMEM (STG * (ABYTES + BBYTES) + 512)

__global__ void __launch_bounds__(256, 1) gemm_mma(const __nv_bfloat16* __restrict__ X,
                                                   const __nv_bfloat16* __restrict__ Y,
                                                   __nv_bfloat16* __restrict__ A) {
    extern __shared__ __align__(16) char dyn[];
    char* sAp = dyn;
    char* sBp = dyn + STG * ABYTES;
    float* sRM = reinterpret_cast<float*>(dyn + STG * (ABYTES + BBYTES));

    const int tid  = threadIdx.x;
    const int wid  = tid >> 5;
    const int lane = tid & 31;
    const int wm   = wid & 1;        // 0..1 -> 64-row slab
    const int wn   = wid >> 1;       // 0..3 -> 64-col slab
    const int i0   = blockIdx.y * BM;
    const int j0   = blockIdx.x * BN;

    if (tid < BM) sRM[tid] = -3.0e38f;

    const uint32_t aBase = smem_to_u32(sAp);
    const uint32_t bBase = smem_to_u32(sBp);

    // A: 512 16B-segments/chunk (2/thread); B: 1024 (4/thread)
    const int ra0 = tid >> 2,         sa0 = tid & 3;
    const int ra1 = (tid + 256) >> 2, sa1 = (tid + 256) & 3;
    const __nv_bfloat16* Xg = X + (size_t)i0 * CC;
    const __nv_bfloat16* Yg = Y + (size_t)j0 * CC;

    auto issue_chunk = [&](int kc, int buf) {
        const uint32_t da = aBase + buf * ABYTES;
        const uint32_t db = bBase + buf * BBYTES;
        const int ko = kc * BK;
        cp_async16(da + ra0 * ROWB + sa0 * 16, Xg + (size_t)ra0 * CC + ko + sa0 * 8);
        cp_async16(da + ra1 * ROWB + sa1 * 16, Xg + (size_t)ra1 * CC + ko + sa1 * 8);
#pragma unroll
        for (int k = 0; k < 4; k++) {
            const int idx = tid + k * 256;
            const int rb = idx >> 2, sb = idx & 3;
            cp_async16(db + rb * ROWB + sb * 16, Yg + (size_t)rb * CC + ko + sb * 8);
        }
        cp_commit();
    };

    float acc[4][8][4];
#pragma unroll
    for (int mt = 0; mt < 4; mt++)
#pragma unroll
        for (int nt = 0; nt < 8; nt++)
#pragma unroll
            for (int q = 0; q < 4; q++) acc[mt][nt][q] = 0.0f;

    issue_chunk(0, 0);
    issue_chunk(1, 1);

    const int aRow = wm * 64 + (lane & 15);
    const uint32_t aColHalf = ((lane >> 4) & 1) * 16;
    const int bRow = wn * 64 + (lane & 7) + ((lane >> 4) & 1) * 8;
    const uint32_t bColHalf = ((lane >> 3) & 1) * 16;

    for (int kc = 0; kc < NKC; kc++) {
        const int buf = kc % STG;
        if (kc + 2 < NKC) { issue_chunk(kc + 2, (kc + 2) % STG); cp_wait<2>(); }
        else if (kc + 1 < NKC) { cp_wait<1>(); }
        else { cp_wait<0>(); }
        __syncthreads();

        const uint32_t ab = aBase + buf * ABYTES;
        const uint32_t bb = bBase + buf * BBYTES;
#pragma unroll
        for (int ks = 0; ks < 2; ks++) {
            uint32_t afr[4][4];
#pragma unroll
            for (int mt = 0; mt < 4; mt++)
                ldmatrix_x4(afr[mt], ab + (uint32_t)(aRow + mt * 16) * ROWB + ks * 32 + aColHalf);
            uint32_t bfr[4][4];
#pragma unroll
            for (int pr = 0; pr < 4; pr++)
                ldmatrix_x4(bfr[pr], bb + (uint32_t)(bRow + pr * 16) * ROWB + ks * 32 + bColHalf);
#pragma unroll
            for (int mt = 0; mt < 4; mt++)
#pragma unroll
                for (int nt = 0; nt < 8; nt++)
                    mma_16816(acc[mt][nt], afr[mt],
                              bfr[nt >> 1][(nt & 1) * 2], bfr[nt >> 1][(nt & 1) * 2 + 1]);
        }
        __syncthreads();
    }

    // ---------------- epilogue: bf16 store + fused row-max ----------------
    const int nb = j0 + wn * 64 + 2 * (lane & 3);
#pragma unroll
    for (int mt = 0; mt < 4; mt++) {
        const int mlo = i0 + wm * 64 + mt * 16 + (lane >> 2);
        float maxlo = -3.0e38f, maxhi = -3.0e38f;
#pragma unroll
        for (int nt = 0; nt < 8; nt++) {
            float c0 = acc[mt][nt][0], c1 = acc[mt][nt][1];
            float c2 = acc[mt][nt][2], c3 = acc[mt][nt][3];
            maxlo = fmaxf(maxlo, fmaxf(c0, c1));
            maxhi = fmaxf(maxhi, fmaxf(c2, c3));
            __nv_bfloat162 lo = __floats2bfloat162_rn(c0, c1);
            __nv_bfloat162 hi = __floats2bfloat162_rn(c2, c3);
            *reinterpret_cast<__nv_bfloat162*>(A + (size_t)mlo * HWN + nb + nt * 8)       = lo;
            *reinterpret_cast<__nv_bfloat162*>(A + (size_t)(mlo + 8) * HWN + nb + nt * 8) = hi;
        }
        maxlo = fmaxf(maxlo, __shfl_xor_sync(0xffffffffu, maxlo, 1));
        maxlo = fmaxf(maxlo, __shfl_xor_sync(0xffffffffu, maxlo, 2));
        maxhi = fmaxf(maxhi, __shfl_xor_sync(0xffffffffu, maxhi, 1));
        maxhi = fmaxf(maxhi, __shfl_xor_sync(0xffffffffu, maxhi, 2));
        if ((lane & 3) == 0) {
            int rl = wm * 64 + mt * 16 + (lane >> 2);
            atomicMaxFloat(&sRM[rl],     maxlo);
            atomicMaxFloat(&sRM[rl + 8], maxhi);
        }
    }
    __syncthreads();
    if (tid < BM) atomicMaxFloat(&g_rowmax[i0 + tid], sRM[tid]);
}

// ---------------- stage 5: per-row exp pass -> k[i] ----------------
// cx_sp == I (spatial branch collapses to identity in fp32; see R2 analysis)
__global__ void cx_row_kernel(const __nv_bfloat16* __restrict__ A) {
    const int row = blockIdx.x;
    const float beta  = 2.0f / (1.0f - g_rowmax[row] + EPS5);
    const float alpha = 2.0f - beta;
    const uint4* Ar = reinterpret_cast<const uint4*>(A + (size_t)row * HWN);
    float s = 0.0f, m = 0.0f;
    for (int q = threadIdx.x; q < HWN / 8; q += blockDim.x) {
        uint4 u = Ar[q];
        const __nv_bfloat162* p = reinterpret_cast<const __nv_bfloat162*>(&u);
#pragma unroll
        for (int t = 0; t < 4; t++) {
            float2 f = __bfloat1622float2(p[t]);
            float w0 = __expf(fmaf(beta, f.x, alpha));
            float w1 = __expf(fmaf(beta, f.y, alpha));
            s += w0 + w1;
            m = fmaxf(m, fmaxf(w0, w1));
        }
    }
    s = blockReduceSum(s);
    m = blockReduceMax(m);
    if (threadIdx.x == 0) {
        float aii = __bfloat162float(A[(size_t)row * HWN + row]);
        float wii = __expf(fmaf(beta, aii, alpha));
        float inv_s = 1.0f / s;
        g_k[row] = fmaxf(0.9f * m * inv_s, fmaf(0.9f * wii, inv_s, 0.1f));
    }
}

// ---------------- stage 6: scalar output ----------------
__global__ void final_kernel(float* __restrict__ out) {
    float s = 0.0f;
    for (int i = threadIdx.x; i < HWN; i += blockDim.x) s += g_k[i];
    s = blockReduceSum(s);
    if (threadIdx.x == 0) out[0] = -logf(s * (1.0f / HWN) + EPS5);
}

// ---------------- launch ----------------
extern "C" void kernel_launch(void* const* d_in, const int* in_sizes, int n_in,
                              void* d_out, int out_size) {
    const float* x = (const float*)d_in[0];
    const float* y = (const float*)d_in[1];
    float* out = (float*)d_out;

    __nv_bfloat16 *pxb, *pyb, *pAb;
    float *pssx, *pssy;
    cudaGetSymbolAddress((void**)&pxb,  g_xb);
    cudaGetSymbolAddress((void**)&pyb,  g_yb);
    cudaGetSymbolAddress((void**)&pAb,  g_Ab);
    cudaGetSymbolAddress((void**)&pssx, g_ssx);
    cudaGetSymbolAddress((void**)&pssy, g_ssy);

    static bool attr_set = false;
    if (!attr_set) {
        cudaFuncSetAttribute(gemm_mma, cudaFuncAttributeMaxDynamicSharedMemorySize, GEMM_SMEM);
        attr_set = true;
    }

    init_kernel<<<HWN / 256, 256>>>();
    ymu_kernel<<<CC, 256>>>(y);
    sumsq_kernel<<<dim3(HWN / 256, CC / 16), 256>>>(x, pssx);
    sumsq_kernel<<<dim3(HWN / 256, CC / 16), 256>>>(y, pssy);
    transpose_kernel<<<dim3(HWN / 32, CC / 32), dim3(32, 8)>>>(x, pssx, pxb);
    transpose_kernel<<<dim3(HWN / 32, CC / 32), dim3(32, 8)>>>(y, pssy, pyb);
    gemm_mma<<<dim3(HWN / BN, HWN / BM), 256, GEMM_SMEM>>>(pxb, pyb, pAb);
    cx_row_kernel<<<HWN, 256>>>(pAb);
    final_kernel<<<1, 256>>>(out);
}

// round 11
// speedup vs baseline: 1.7471x; 1.1642x over previous
#include <cuda_runtime.h>
#include <cuda_bf16.h>
#include <cstdint>
#include <math.h>

#define CC   512
#define HWN  6400
#define EPS5 1e-5f

// ---------------- device scratch (no runtime allocation allowed) ----------------
__device__ float g_ymu [CC];
__device__ float g_ssx [HWN];                      // per-pixel sum of squares (x)
__device__ float g_ssy [HWN];
__device__ __nv_bfloat16 g_xb[HWN * CC];           // xn transposed [i][c], bf16
__device__ __nv_bfloat16 g_yb[HWN * CC];           // yn transposed [j][c], bf16
__device__ __nv_bfloat16 g_Ab[(size_t)HWN * HWN];  // 6400x6400 bf16 Gram (81.92 MB)
__device__ float g_rowmax[HWN];
__device__ float g_k   [HWN];

// ---------------- helpers ----------------
__device__ __forceinline__ uint32_t smem_to_u32(const void* smem_ptr) {
    uint32_t addr;
    asm("{ .reg .u64 tmp; cvta.to.shared.u64 tmp, %1; cvt.u32.u64 %0, tmp; }"
        : "=r"(addr) : "l"(smem_ptr));
    return addr;
}
__device__ __forceinline__ void cp_async16(uint32_t dst, const void* src) {
    asm volatile("cp.async.cg.shared.global [%0], [%1], 16;" :: "r"(dst), "l"(src) : "memory");
}
__device__ __forceinline__ void cp_commit() {
    asm volatile("cp.async.commit_group;" ::: "memory");
}
template<int N>
__device__ __forceinline__ void cp_wait() {
    asm volatile("cp.async.wait_group %0;" :: "n"(N) : "memory");
}
__device__ __forceinline__ void ldmatrix_x4(uint32_t* r, uint32_t addr) {
    asm volatile("ldmatrix.sync.aligned.m8n8.x4.shared.b16 {%0,%1,%2,%3}, [%4];"
        : "=r"(r[0]), "=r"(r[1]), "=r"(r[2]), "=r"(r[3]) : "r"(addr));
}
__device__ __forceinline__ void mma_16816(float* c, const uint32_t* a,
                                          uint32_t b0, uint32_t b1) {
    asm volatile(
        "mma.sync.aligned.m16n8k16.row.col.f32.bf16.bf16.f32 "
        "{%0,%1,%2,%3}, {%4,%5,%6,%7}, {%8,%9}, {%0,%1,%2,%3};"
        : "+f"(c[0]), "+f"(c[1]), "+f"(c[2]), "+f"(c[3])
        : "r"(a[0]), "r"(a[1]), "r"(a[2]), "r"(a[3]), "r"(b0), "r"(b1));
}
__device__ __forceinline__ void atomicMaxFloat(float* addr, float v) {
    if (v >= 0.0f) atomicMax((int*)addr, __float_as_int(v));
    else           atomicMin((unsigned int*)addr, __float_as_uint(v));
}

// ---------------- reductions ----------------
__device__ __forceinline__ float warpReduceSum(float v) {
#pragma unroll
    for (int o = 16; o > 0; o >>= 1) v += __shfl_xor_sync(0xffffffffu, v, o);
    return v;
}
__device__ __forceinline__ float warpReduceMax(float v) {
#pragma unroll
    for (int o = 16; o > 0; o >>= 1) v = fmaxf(v, __shfl_xor_sync(0xffffffffu, v, o));
    return v;
}
__device__ __forceinline__ float blockReduceSum(float v) {
    __shared__ float sh[8];
    int lane = threadIdx.x & 31, w = threadIdx.x >> 5;
    v = warpReduceSum(v);
    if (lane == 0) sh[w] = v;
    __syncthreads();
    v = (threadIdx.x < 8) ? sh[threadIdx.x] : 0.0f;
    if (w == 0) v = warpReduceSum(v);
    __syncthreads();
    return v;
}
__device__ __forceinline__ float blockReduceMax(float v) {
    __shared__ float sh[8];
    int lane = threadIdx.x & 31, w = threadIdx.x >> 5;
    v = warpReduceMax(v);
    if (lane == 0) sh[w] = v;
    __syncthreads();
    v = (threadIdx.x < 8) ? sh[threadIdx.x] : -3.0e38f;
    if (w == 0) v = warpReduceMax(v);
    __syncthreads();
    return v;
}

// ---------------- stage 0: init (rowmax = -inf, ss = 0) ----------------
__global__ void init_kernel() {
    const int i = blockIdx.x * 256 + threadIdx.x;
    g_rowmax[i] = -3.0e38f;
    g_ssx[i] = 0.0f;
    g_ssy[i] = 0.0f;
}

// ---------------- stage 1: per-channel mean of y ----------------
__global__ void ymu_kernel(const float* __restrict__ y) {
    const int c = blockIdx.x;
    const float4* row = reinterpret_cast<const float4*>(y + (size_t)c * HWN);
    float s = 0.0f;
    for (int j = threadIdx.x; j < HWN / 4; j += blockDim.x) {
        float4 v = row[j];
        s += (v.x + v.y) + (v.z + v.w);
    }
    s = blockReduceSum(s);
    if (threadIdx.x == 0) g_ymu[c] = s * (1.0f / HWN);
}

// ---------------- stage 2: per-pixel partial sum of squares (16-ch slabs) ----------------
__global__ void sumsq_kernel(const float* __restrict__ v, float* __restrict__ ss) {
    __shared__ float smu[16];
    const int c0 = blockIdx.y * 16;
    if (threadIdx.x < 16) smu[threadIdx.x] = g_ymu[c0 + threadIdx.x];
    __syncthreads();
    const int i = blockIdx.x * 256 + threadIdx.x;
    float s = 0.0f;
#pragma unroll
    for (int c = 0; c < 16; c++) {
        float t = v[(size_t)(c0 + c) * HWN + i] - smu[c];
        s = fmaf(t, t, s);
    }
    atomicAdd(&ss[i], s);
}

// ---------------- stage 3: center+scale+transpose to bf16 [i][c] ----------------
__global__ void transpose_kernel(const float* __restrict__ v, const float* __restrict__ ss,
                                 __nv_bfloat16* __restrict__ o) {
    __shared__ float tile[32][33];
    __shared__ float mu[32], sinv[32];
    const int i0 = blockIdx.x * 32;
    const int c0 = blockIdx.y * 32;
    const int tx = threadIdx.x, ty = threadIdx.y;   // (32, 8)
    if (ty == 0) {
        mu[tx] = g_ymu[c0 + tx];
        sinv[tx] = 1.0f / fmaxf(sqrtf(ss[i0 + tx]), 1e-12f);
    }
    __syncthreads();
#pragma unroll
    for (int r = 0; r < 4; r++) {
        int cl = ty + 8 * r;
        tile[cl][tx] = (v[(size_t)(c0 + cl) * HWN + i0 + tx] - mu[cl]) * sinv[tx];
    }
    __syncthreads();
#pragma unroll
    for (int r = 0; r < 4; r++) {
        int il = ty + 8 * r;
        o[(size_t)(i0 + il) * CC + c0 + tx] = __float2bfloat16(tile[tx][il]);
    }
}

// ---------------- stage 4: bf16 warp-MMA GEMM A = Xb * Yb^T ----------------
// CTA tile 256(M) x 128(N), 512 threads, 16 warps 4(m) x 4(n),
// warp tile 64x32 (acc = 64 regs), BK=32, 3-stage cp.async, rows padded 80 B.
#define BM 256
#define BN 128
#define BK 32
#define ROWB 80          // 32 bf16 = 64B data + 16B pad
#define NKC (CC / BK)    // 16 k-chunks
#define STG 3
#define ABYTES (BM * ROWB)
#define BBYTES (BN * ROWB)
#define GEMM_SMEM (STG * (ABYTES + BBYTES) + 1152)

__global__ void __launch_bounds__(512, 1) gemm_mma(const __nv_bfloat16* __restrict__ X,
                                                   const __nv_bfloat16* __restrict__ Y,
                                                   __nv_bfloat16* __restrict__ A) {
    extern __shared__ __align__(16) char dyn[];
    char* sAp = dyn;
    char* sBp = dyn + STG * ABYTES;
    float* sRM = reinterpret_cast<float*>(dyn + STG * (ABYTES + BBYTES));

    const int tid  = threadIdx.x;
    const int wid  = tid >> 5;
    const int lane = tid & 31;
    const int wm   = wid & 3;        // 0..3 -> 64-row slab
    const int wn   = wid >> 2;       // 0..3 -> 32-col slab
    const int i0   = blockIdx.y * BM;
    const int j0   = blockIdx.x * BN;

    if (tid < BM) sRM[tid] = -3.0e38f;

    const uint32_t aBase = smem_to_u32(sAp);
    const uint32_t bBase = smem_to_u32(sBp);

    // A: 1024 16B-segments/chunk (2/thread); B: 512 (1/thread)
    const int ra0 = tid >> 2,         sa0 = tid & 3;
    const int ra1 = (tid + 512) >> 2, sa1 = (tid + 512) & 3;
    const __nv_bfloat16* Xg = X + (size_t)i0 * CC;
    const __nv_bfloat16* Yg = Y + (size_t)j0 * CC;

    auto issue_chunk = [&](int kc, int buf) {
        const uint32_t da = aBase + buf * ABYTES;
        const uint32_t db = bBase + buf * BBYTES;
        const int ko = kc * BK;
        cp_async16(da + ra0 * ROWB + sa0 * 16, Xg + (size_t)ra0 * CC + ko + sa0 * 8);
        cp_async16(da + ra1 * ROWB + sa1 * 16, Xg + (size_t)ra1 * CC + ko + sa1 * 8);
        cp_async16(db + ra0 * ROWB + sa0 * 16, Yg + (size_t)ra0 * CC + ko + sa0 * 8);
        cp_commit();
    };

    float acc[4][4][4];
#pragma unroll
    for (int mt = 0; mt < 4; mt++)
#pragma unroll
        for (int nt = 0; nt < 4; nt++)
#pragma unroll
            for (int q = 0; q < 4; q++) acc[mt][nt][q] = 0.0f;

    issue_chunk(0, 0);
    issue_chunk(1, 1);

    const int aRow = wm * 64 + (lane & 15);
    const uint32_t aColHalf = ((lane >> 4) & 1) * 16;
    const int bRow = wn * 32 + (lane & 7) + ((lane >> 4) & 1) * 8;
    const uint32_t bColHalf = ((lane >> 3) & 1) * 16;

    for (int kc = 0; kc < NKC; kc++) {
        const int buf = kc % STG;
        if (kc + 2 < NKC) { issue_chunk(kc + 2, (kc + 2) % STG); cp_wait<2>(); }
        else if (kc + 1 < NKC) { cp_wait<1>(); }
        else { cp_wait<0>(); }
        __syncthreads();

        const uint32_t ab = aBase + buf * ABYTES;
        const uint32_t bb = bBase + buf * BBYTES;
#pragma unroll
        for (int ks = 0; ks < 2; ks++) {
            uint32_t afr[4][4];
#pragma unroll
            for (int mt = 0; mt < 4; mt++)
                ldmatrix_x4(afr[mt], ab + (uint32_t)(aRow + mt * 16) * ROWB + ks * 32 + aColHalf);
            uint32_t bfr[2][4];
#pragma unroll
            for (int pr = 0; pr < 2; pr++)
                ldmatrix_x4(bfr[pr], bb + (uint32_t)(bRow + pr * 16) * ROWB + ks * 32 + bColHalf);
#pragma unroll
            for (int mt = 0; mt < 4; mt++)
#pragma unroll
                for (int nt = 0; nt < 4; nt++)
                    mma_16816(acc[mt][nt], afr[mt],
                              bfr[nt >> 1][(nt & 1) * 2], bfr[nt >> 1][(nt & 1) * 2 + 1]);
        }
        __syncthreads();
    }

    // ---------------- epilogue: bf16 store + fused row-max ----------------
    const int nb = j0 + wn * 32 + 2 * (lane & 3);
#pragma unroll
    for (int mt = 0; mt < 4; mt++) {
        const int mlo = i0 + wm * 64 + mt * 16 + (lane >> 2);
        float maxlo = -3.0e38f, maxhi = -3.0e38f;
#pragma unroll
        for (int nt = 0; nt < 4; nt++) {
            float c0 = acc[mt][nt][0], c1 = acc[mt][nt][1];
            float c2 = acc[mt][nt][2], c3 = acc[mt][nt][3];
            maxlo = fmaxf(maxlo, fmaxf(c0, c1));
            maxhi = fmaxf(maxhi, fmaxf(c2, c3));
            __nv_bfloat162 lo = __floats2bfloat162_rn(c0, c1);
            __nv_bfloat162 hi = __floats2bfloat162_rn(c2, c3);
            *reinterpret_cast<__nv_bfloat162*>(A + (size_t)mlo * HWN + nb + nt * 8)       = lo;
            *reinterpret_cast<__nv_bfloat162*>(A + (size_t)(mlo + 8) * HWN + nb + nt * 8) = hi;
        }
        maxlo = fmaxf(maxlo, __shfl_xor_sync(0xffffffffu, maxlo, 1));
        maxlo = fmaxf(maxlo, __shfl_xor_sync(0xffffffffu, maxlo, 2));
        maxhi = fmaxf(maxhi, __shfl_xor_sync(0xffffffffu, maxhi, 1));
        maxhi = fmaxf(maxhi, __shfl_xor_sync(0xffffffffu, maxhi, 2));
        if ((lane & 3) == 0) {
            int rl = wm * 64 + mt * 16 + (lane >> 2);
            atomicMaxFloat(&sRM[rl],     maxlo);
            atomicMaxFloat(&sRM[rl + 8], maxhi);
        }
    }
    __syncthreads();
    if (tid < BM) atomicMaxFloat(&g_rowmax[i0 + tid], sRM[tid]);
}

// ---------------- stage 5: per-row exp pass -> k[i] ----------------
// cx_sp == I (spatial branch collapses to identity in fp32; see R2 analysis)
__global__ void cx_row_kernel(const __nv_bfloat16* __restrict__ A) {
    const int row = blockIdx.x;
    const float beta  = 2.0f / (1.0f - g_rowmax[row] + EPS5);
    const float alpha = 2.0f - beta;
    const uint4* Ar = reinterpret_cast<const uint4*>(A + (size_t)row * HWN);
    float s = 0.0f, m = 0.0f;
    for (int q = threadIdx.x; q < HWN / 8; q += blockDim.x) {
        uint4 u = Ar[q];
        const __nv_bfloat162* p = reinterpret_cast<const __nv_bfloat162*>(&u);
#pragma unroll
        for (int t = 0; t < 4; t++) {
            float2 f = __bfloat1622float2(p[t]);
            float w0 = __expf(fmaf(beta, f.x, alpha));
            float w1 = __expf(fmaf(beta, f.y, alpha));
            s += w0 + w1;
            m = fmaxf(m, fmaxf(w0, w1));
        }
    }
    s = blockReduceSum(s);
    m = blockReduceMax(m);
    if (threadIdx.x == 0) {
        float aii = __bfloat162float(A[(size_t)row * HWN + row]);
        float wii = __expf(fmaf(beta, aii, alpha));
        float inv_s = 1.0f / s;
        g_k[row] = fmaxf(0.9f * m * inv_s, fmaf(0.9f * wii, inv_s, 0.1f));
    }
}

// ---------------- stage 6: scalar output ----------------
__global__ void final_kernel(float* __restrict__ out) {
    float s = 0.0f;
    for (int i = threadIdx.x; i < HWN; i += blockDim.x) s += g_k[i];
    s = blockReduceSum(s);
    if (threadIdx.x == 0) out[0] = -logf(s * (1.0f / HWN) + EPS5);
}

// ---------------- launch ----------------
extern "C" void kernel_launch(void* const* d_in, const int* in_sizes, int n_in,
                              void* d_out, int out_size) {
    const float* x = (const float*)d_in[0];
    const float* y = (const float*)d_in[1];
    float* out = (float*)d_out;

    __nv_bfloat16 *pxb, *pyb, *pAb;
    float *pssx, *pssy;
    cudaGetSymbolAddress((void**)&pxb,  g_xb);
    cudaGetSymbolAddress((void**)&pyb,  g_yb);
    cudaGetSymbolAddress((void**)&pAb,  g_Ab);
    cudaGetSymbolAddress((void**)&pssx, g_ssx);
    cudaGetSymbolAddress((void**)&pssy, g_ssy);

    static bool attr_set = false;
    if (!attr_set) {
        cudaFuncSetAttribute(gemm_mma, cudaFuncAttributeMaxDynamicSharedMemorySize, GEMM_SMEM);
        attr_set = true;
    }

    init_kernel<<<HWN / 256, 256>>>();
    ymu_kernel<<<CC, 256>>>(y);
    sumsq_kernel<<<dim3(HWN / 256, CC / 16), 256>>>(x, pssx);
    sumsq_kernel<<<dim3(HWN / 256, CC / 16), 256>>>(y, pssy);
    transpose_kernel<<<dim3(HWN / 32, CC / 32), dim3(32, 8)>>>(x, pssx, pxb);
    transpose_kernel<<<dim3(HWN / 32, CC / 32), dim3(32, 8)>>>(y, pssy, pyb);
    gemm_mma<<<dim3(HWN / BN, HWN / BM), 512, GEMM_SMEM>>>(pxb, pyb, pAb);
    cx_row_kernel<<<HWN, 256>>>(pAb);
    final_kernel<<<1, 256>>>(out);
}

// round 13
// speedup vs baseline: 1.8377x; 1.0518x over previous
#include <cuda_runtime.h>
#include <cuda_bf16.h>
#include <cstdint>
#include <math.h>

#define CC   512
#define HWN  6400
#define EPS5 1e-5f

// ---------------- device scratch (no runtime allocation allowed) ----------------
__device__ float g_ymu [CC];
__device__ float g_sinvx[HWN];                     // 1/norm per pixel (x)
__device__ float g_sinvy[HWN];
__device__ __nv_bfloat16 g_xb[HWN * CC];           // centered x, transposed [i][c], bf16
__device__ __nv_bfloat16 g_yb[HWN * CC];           // centered y, transposed [j][c], bf16
__device__ __nv_bfloat16 g_Ab[(size_t)HWN * HWN];  // 6400x6400 bf16 Gram (81.92 MB)
__device__ float g_rowmax[HWN];
__device__ float g_k   [HWN];

// ---------------- helpers ----------------
__device__ __forceinline__ uint32_t smem_to_u32(const void* smem_ptr) {
    uint32_t addr;
    asm("{ .reg .u64 tmp; cvta.to.shared.u64 tmp, %1; cvt.u32.u64 %0, tmp; }"
        : "=r"(addr) : "l"(smem_ptr));
    return addr;
}
__device__ __forceinline__ void cp_async16(uint32_t dst, const void* src) {
    asm volatile("cp.async.cg.shared.global [%0], [%1], 16;" :: "r"(dst), "l"(src) : "memory");
}
__device__ __forceinline__ void cp_commit() {
    asm volatile("cp.async.commit_group;" ::: "memory");
}
template<int N>
__device__ __forceinline__ void cp_wait() {
    asm volatile("cp.async.wait_group %0;" :: "n"(N) : "memory");
}
__device__ __forceinline__ void ldmatrix_x4(uint32_t* r, uint32_t addr) {
    asm volatile("ldmatrix.sync.aligned.m8n8.x4.shared.b16 {%0,%1,%2,%3}, [%4];"
        : "=r"(r[0]), "=r"(r[1]), "=r"(r[2]), "=r"(r[3]) : "r"(addr));
}
__device__ __forceinline__ void mma_16816(float* c, const uint32_t* a,
                                          uint32_t b0, uint32_t b1) {
    asm volatile(
        "mma.sync.aligned.m16n8k16.row.col.f32.bf16.bf16.f32 "
        "{%0,%1,%2,%3}, {%4,%5,%6,%7}, {%8,%9}, {%0,%1,%2,%3};"
        : "+f"(c[0]), "+f"(c[1]), "+f"(c[2]), "+f"(c[3])
        : "r"(a[0]), "r"(a[1]), "r"(a[2]), "r"(a[3]), "r"(b0), "r"(b1));
}
__device__ __forceinline__ void atomicMaxFloat(float* addr, float v) {
    if (v >= 0.0f) atomicMax((int*)addr, __float_as_int(v));
    else           atomicMin((unsigned int*)addr, __float_as_uint(v));
}

// ---------------- reductions ----------------
__device__ __forceinline__ float warpReduceSum(float v) {
#pragma unroll
    for (int o = 16; o > 0; o >>= 1) v += __shfl_xor_sync(0xffffffffu, v, o);
    return v;
}
__device__ __forceinline__ float warpReduceMax(float v) {
#pragma unroll
    for (int o = 16; o > 0; o >>= 1) v = fmaxf(v, __shfl_xor_sync(0xffffffffu, v, o));
    return v;
}
__device__ __forceinline__ float blockReduceSum(float v) {
    __shared__ float sh[8];
    int lane = threadIdx.x & 31, w = threadIdx.x >> 5;
    v = warpReduceSum(v);
    if (lane == 0) sh[w] = v;
    __syncthreads();
    v = (threadIdx.x < 8) ? sh[threadIdx.x] : 0.0f;
    if (w == 0) v = warpReduceSum(v);
    __syncthreads();
    return v;
}
__device__ __forceinline__ float blockReduceMax(float v) {
    __shared__ float sh[8];
    int lane = threadIdx.x & 31, w = threadIdx.x >> 5;
    v = warpReduceMax(v);
    if (lane == 0) sh[w] = v;
    __syncthreads();
    v = (threadIdx.x < 8) ? sh[threadIdx.x] : -3.0e38f;
    if (w == 0) v = warpReduceMax(v);
    __syncthreads();
    return v;
}

// ---------------- stage 0: init rowmax ----------------
__global__ void init_kernel() {
    g_rowmax[blockIdx.x * 256 + threadIdx.x] = -3.0e38f;
}

// ---------------- stage 1: per-channel mean of y ----------------
__global__ void ymu_kernel(const float* __restrict__ y) {
    const int c = blockIdx.x;
    const float4* row = reinterpret_cast<const float4*>(y + (size_t)c * HWN);
    float s = 0.0f;
    for (int j = threadIdx.x; j < HWN / 4; j += blockDim.x) {
        float4 v = row[j];
        s += (v.x + v.y) + (v.z + v.w);
    }
    s = blockReduceSum(s);
    if (threadIdx.x == 0) g_ymu[c] = s * (1.0f / HWN);
}

// ---------------- stage 2: center + transpose to bf16 [i][c] (no scale) ----------------
__global__ void transpose_kernel(const float* __restrict__ v, __nv_bfloat16* __restrict__ o) {
    __shared__ float tile[32][33];
    __shared__ float mu[32];
    const int i0 = blockIdx.x * 32;
    const int c0 = blockIdx.y * 32;
    const int tx = threadIdx.x, ty = threadIdx.y;   // (32, 8)
    if (ty == 0) mu[tx] = g_ymu[c0 + tx];
    __syncthreads();
#pragma unroll
    for (int r = 0; r < 4; r++) {
        int cl = ty + 8 * r;
        tile[cl][tx] = v[(size_t)(c0 + cl) * HWN + i0 + tx] - mu[cl];
    }
    __syncthreads();
#pragma unroll
    for (int r = 0; r < 4; r++) {
        int il = ty + 8 * r;
        o[(size_t)(i0 + il) * CC + c0 + tx] = __float2bfloat16(tile[tx][il]);
    }
}

// ---------------- stage 3: per-row inverse norm from bf16 rows ----------------
// warp per row; rows are contiguous (512 bf16 = 1KB), fully coalesced.
__global__ void rownorm_kernel(const __nv_bfloat16* __restrict__ b, float* __restrict__ sinv) {
    const int row  = blockIdx.x * 8 + (threadIdx.x >> 5);
    const int lane = threadIdx.x & 31;
    const uint4* r = reinterpret_cast<const uint4*>(b + (size_t)row * CC);
    float s = 0.0f;
#pragma unroll
    for (int q = 0; q < 2; q++) {
        uint4 u = r[lane + q * 32];
        const __nv_bfloat162* p = reinterpret_cast<const __nv_bfloat162*>(&u);
#pragma unroll
        for (int t = 0; t < 4; t++) {
            float2 f = __bfloat1622float2(p[t]);
            s = fmaf(f.x, f.x, s);
            s = fmaf(f.y, f.y, s);
        }
    }
    s = warpReduceSum(s);
    if (lane == 0) sinv[row] = 1.0f / fmaxf(sqrtf(s), 1e-12f);
}

// ---------------- stage 4: bf16 warp-MMA GEMM A = sx_i sy_j (Xb_i . Yb_j) ----------------
// CTA tile 128x128, 8 warps 2(m) x 4(n), warp tile 64x32, BK=32,
// 3-stage cp.async pipeline, rows padded to 80 B, 2 CTAs/SM. (R8 config)
#define BM 128
#define BN 128
#define BK 32
#define ROWB 80          // 32 bf16 = 64B data + 16B pad
#define NKC (CC / BK)    // 16 k-chunks
#define STG 3
#define ABYTES (BM * ROWB)
#define BBYTES (BN * ROWB)
#define GEMM_SMEM (STG * (ABYTES + BBYTES) + 512)

__global__ void __launch_bounds__(256, 2) gemm_mma(const __nv_bfloat16* __restrict__ X,
                                                   const __nv_bfloat16* __restrict__ Y,
                                                   __nv_bfloat16* __restrict__ A) {
    extern __shared__ __align__(16) char dyn[];
    char* sAp = dyn;
    char* sBp = dyn + STG * ABYTES;
    float* sRM = reinterpret_cast<float*>(dyn + STG * (ABYTES + BBYTES));

    const int tid  = threadIdx.x;
    const int wid  = tid >> 5;
    const int lane = tid & 31;
    const int wm   = wid & 1;        // 0..1 -> 64-row slab
    const int wn   = wid >> 1;       // 0..3 -> 32-col slab
    const int i0   = blockIdx.y * BM;
    const int j0   = blockIdx.x * BN;

    if (tid < BM) sRM[tid] = -3.0e38f;

    const uint32_t aBase = smem_to_u32(sAp);
    const uint32_t bBase = smem_to_u32(sBp);

    const int r0 = tid >> 2,         s0 = tid & 3;
    const int r1 = (tid + 256) >> 2, s1 = (tid + 256) & 3;
    const __nv_bfloat16* Xg = X + (size_t)i0 * CC;
    const __nv_bfloat16* Yg = Y + (size_t)j0 * CC;

    auto issue_chunk = [&](int kc, int buf) {
        const uint32_t da = aBase + buf * ABYTES;
        const uint32_t db = bBase + buf * BBYTES;
        const int ko = kc * BK;
        cp_async16(da + r0 * ROWB + s0 * 16, Xg + (size_t)r0 * CC + ko + s0 * 8);
        cp_async16(da + r1 * ROWB + s1 * 16, Xg + (size_t)r1 * CC + ko + s1 * 8);
        cp_async16(db + r0 * ROWB + s0 * 16, Yg + (size_t)r0 * CC + ko + s0 * 8);
        cp_async16(db + r1 * ROWB + s1 * 16, Yg + (size_t)r1 * CC + ko + s1 * 8);
        cp_commit();
    };

    float acc[4][4][4];
#pragma unroll
    for (int mt = 0; mt < 4; mt++)
#pragma unroll
        for (int nt = 0; nt < 4; nt++)
#pragma unroll
            for (int q = 0; q < 4; q++) acc[mt][nt][q] = 0.0f;

    issue_chunk(0, 0);
    issue_chunk(1, 1);

    const int aRow = wm * 64 + (lane & 15);
    const uint32_t aColHalf = ((lane >> 4) & 1) * 16;
    const int bRow = wn * 32 + (lane & 7) + ((lane >> 4) & 1) * 8;
    const uint32_t bColHalf = ((lane >> 3) & 1) * 16;

    for (int kc = 0; kc < NKC; kc++) {
        const int buf = kc % STG;
        if (kc + 2 < NKC) { issue_chunk(kc + 2, (kc + 2) % STG); cp_wait<2>(); }
        else if (kc + 1 < NKC) { cp_wait<1>(); }
        else { cp_wait<0>(); }
        __syncthreads();

        const uint32_t ab = aBase + buf * ABYTES;
        const uint32_t bb = bBase + buf * BBYTES;
#pragma unroll
        for (int ks = 0; ks < 2; ks++) {
            uint32_t afr[4][4];
#pragma unroll
            for (int mt = 0; mt < 4; mt++)
                ldmatrix_x4(afr[mt], ab + (uint32_t)(aRow + mt * 16) * ROWB + ks * 32 + aColHalf);
            uint32_t bfr[2][4];
#pragma unroll
            for (int pr = 0; pr < 2; pr++)
                ldmatrix_x4(bfr[pr], bb + (uint32_t)(bRow + pr * 16) * ROWB + ks * 32 + bColHalf);
#pragma unroll
            for (int mt = 0; mt < 4; mt++)
#pragma unroll
                for (int nt = 0; nt < 4; nt++)
                    mma_16816(acc[mt][nt], afr[mt],
                              bfr[nt >> 1][(nt & 1) * 2], bfr[nt >> 1][(nt & 1) * 2 + 1]);
        }
        __syncthreads();
    }

    // ---------------- epilogue: scale + bf16 store + fused row-max ----------------
    const int nb = j0 + wn * 32 + 2 * (lane & 3);
    float sy0[4], sy1[4];
#pragma unroll
    for (int nt = 0; nt < 4; nt++) {
        sy0[nt] = g_sinvy[nb + nt * 8];
        sy1[nt] = g_sinvy[nb + nt * 8 + 1];
    }
#pragma unroll
    for (int mt = 0; mt < 4; mt++) {
        const int mlo = i0 + wm * 64 + mt * 16 + (lane >> 2);
        const float sxlo = g_sinvx[mlo];
        const float sxhi = g_sinvx[mlo + 8];
        float maxlo = -3.0e38f, maxhi = -3.0e38f;
#pragma unroll
        for (int nt = 0; nt < 4; nt++) {
            float c0 = acc[mt][nt][0] * sxlo * sy0[nt];
            float c1 = acc[mt][nt][1] * sxlo * sy1[nt];
            float c2 = acc[mt][nt][2] * sxhi * sy0[nt];
            float c3 = acc[mt][nt][3] * sxhi * sy1[nt];
            maxlo = fmaxf(maxlo, fmaxf(c0, c1));
            maxhi = fmaxf(maxhi, fmaxf(c2, c3));
            __nv_bfloat162 lo = __floats2bfloat162_rn(c0, c1);
            __nv_bfloat162 hi = __floats2bfloat162_rn(c2, c3);
            *reinterpret_cast<__nv_bfloat162*>(A + (size_t)mlo * HWN + nb + nt * 8)       = lo;
            *reinterpret_cast<__nv_bfloat162*>(A + (size_t)(mlo + 8) * HWN + nb + nt * 8) = hi;
        }
        maxlo = fmaxf(maxlo, __shfl_xor_sync(0xffffffffu, maxlo, 1));
        maxlo = fmaxf(maxlo, __shfl_xor_sync(0xffffffffu, maxlo, 2));
        maxhi = fmaxf(maxhi, __shfl_xor_sync(0xffffffffu, maxhi, 1));
        maxhi = fmaxf(maxhi, __shfl_xor_sync(0xffffffffu, maxhi, 2));
        if ((lane & 3) == 0) {
            int rl = wm * 64 + mt * 16 + (lane >> 2);
            atomicMaxFloat(&sRM[rl],     maxlo);
            atomicMaxFloat(&sRM[rl + 8], maxhi);
        }
    }
    __syncthreads();
    if (tid < BM) atomicMaxFloat(&g_rowmax[i0 + tid], sRM[tid]);
}

// ---------------- stage 5: per-row exp pass -> k[i] ----------------
// cx_sp == I (spatial branch collapses to identity in fp32; see R2 analysis)
__global__ void cx_row_kernel(const __nv_bfloat16* __restrict__ A) {
    const int row = blockIdx.x;
    const float beta  = 2.0f / (1.0f - g_rowmax[row] + EPS5);
    const float alpha = 2.0f - beta;
    const uint4* Ar = reinterpret_cast<const uint4*>(A + (size_t)row * HWN);
    float s = 0.0f, m = 0.0f;
    for (int q = threadIdx.x; q < HWN / 8; q += blockDim.x) {
        uint4 u = Ar[q];
        const __nv_bfloat162* p = reinterpret_cast<const __nv_bfloat162*>(&u);
#pragma unroll
        for (int t = 0; t < 4; t++) {
            float2 f = __bfloat1622float2(p[t]);
            float w0 = __expf(fmaf(beta, f.x, alpha));
            float w1 = __expf(fmaf(beta, f.y, alpha));
            s += w0 + w1;
            m = fmaxf(m, fmaxf(w0, w1));
        }
    }
    s = blockReduceSum(s);
    m = blockReduceMax(m);
    if (threadIdx.x == 0) {
        float aii = __bfloat162float(A[(size_t)row * HWN + row]);
        float wii = __expf(fmaf(beta, aii, alpha));
        float inv_s = 1.0f / s;
        g_k[row] = fmaxf(0.9f * m * inv_s, fmaf(0.9f * wii, inv_s, 0.1f));
    }
}

// ---------------- stage 6: scalar output ----------------
__global__ void final_kernel(float* __restrict__ out) {
    float s = 0.0f;
    for (int i = threadIdx.x; i < HWN; i += blockDim.x) s += g_k[i];
    s = blockReduceSum(s);
    if (threadIdx.x == 0) out[0] = -logf(s * (1.0f / HWN) + EPS5);
}

// ---------------- launch ----------------
extern "C" void kernel_launch(void* const* d_in, const int* in_sizes, int n_in,
                              void* d_out, int out_size) {
    const float* x = (const float*)d_in[0];
    const float* y = (const float*)d_in[1];
    float* out = (float*)d_out;

    __nv_bfloat16 *pxb, *pyb, *pAb;
    float *psx, *psy;
    cudaGetSymbolAddress((void**)&pxb, g_xb);
    cudaGetSymbolAddress((void**)&pyb, g_yb);
    cudaGetSymbolAddress((void**)&pAb, g_Ab);
    cudaGetSymbolAddress((void**)&psx, g_sinvx);
    cudaGetSymbolAddress((void**)&psy, g_sinvy);

    static bool attr_set = false;
    if (!attr_set) {
        cudaFuncSetAttribute(gemm_mma, cudaFuncAttributeMaxDynamicSharedMemorySize, GEMM_SMEM);
        attr_set = true;
    }

    init_kernel<<<HWN / 256, 256>>>();
    ymu_kernel<<<CC, 256>>>(y);
    transpose_kernel<<<dim3(HWN / 32, CC / 32), dim3(32, 8)>>>(x, pxb);
    transpose_kernel<<<dim3(HWN / 32, CC / 32), dim3(32, 8)>>>(y, pyb);
    rownorm_kernel<<<HWN / 8, 256>>>(pxb, psx);
    rownorm_kernel<<<HWN / 8, 256>>>(pyb, psy);
    gemm_mma<<<dim3(HWN / BN, HWN / BM), 256, GEMM_SMEM>>>(pxb, pyb, pAb);
    cx_row_kernel<<<HWN, 256>>>(pAb);
    final_kernel<<<1, 256>>>(out);
}

// round 15
// speedup vs baseline: 1.9568x; 1.0648x over previous
#include <cuda_runtime.h>
#include <cuda_bf16.h>
#include <cuda_fp16.h>
#include <cstdint>
#include <math.h>

#define CC   512
#define HWN  6400
#define EPS5 1e-5f

// ---------------- device scratch (no runtime allocation allowed) ----------------
__device__ float g_ymu [CC];
__device__ float g_sinvx[HWN];                     // 1/norm per pixel (x)
__device__ float g_sinvy[HWN];
__device__ __nv_bfloat16 g_xb[HWN * CC];           // centered x, transposed [i][c], bf16
__device__ __nv_bfloat16 g_yb[HWN * CC];           // centered y, transposed [j][c], bf16
__device__ uint8_t g_A8[(size_t)HWN * HWN];        // 6400x6400 e4m3 Gram (40.96 MB)
__device__ float g_rowmax[HWN];
__device__ float g_k   [HWN];

// ---------------- helpers ----------------
__device__ __forceinline__ uint32_t smem_to_u32(const void* smem_ptr) {
    uint32_t addr;
    asm("{ .reg .u64 tmp; cvta.to.shared.u64 tmp, %1; cvt.u32.u64 %0, tmp; }"
        : "=r"(addr) : "l"(smem_ptr));
    return addr;
}
__device__ __forceinline__ void cp_async16(uint32_t dst, const void* src) {
    asm volatile("cp.async.cg.shared.global [%0], [%1], 16;" :: "r"(dst), "l"(src) : "memory");
}
__device__ __forceinline__ void cp_commit() {
    asm volatile("cp.async.commit_group;" ::: "memory");
}
template<int N>
__device__ __forceinline__ void cp_wait() {
    asm volatile("cp.async.wait_group %0;" :: "n"(N) : "memory");
}
__device__ __forceinline__ void ldmatrix_x4(uint32_t* r, uint32_t addr) {
    asm volatile("ldmatrix.sync.aligned.m8n8.x4.shared.b16 {%0,%1,%2,%3}, [%4];"
        : "=r"(r[0]), "=r"(r[1]), "=r"(r[2]), "=r"(r[3]) : "r"(addr));
}
__device__ __forceinline__ void mma_16816(float* c, const uint32_t* a,
                                          uint32_t b0, uint32_t b1) {
    asm volatile(
        "mma.sync.aligned.m16n8k16.row.col.f32.bf16.bf16.f32 "
        "{%0,%1,%2,%3}, {%4,%5,%6,%7}, {%8,%9}, {%0,%1,%2,%3};"
        : "+f"(c[0]), "+f"(c[1]), "+f"(c[2]), "+f"(c[3])
        : "r"(a[0]), "r"(a[1]), "r"(a[2]), "r"(a[3]), "r"(b0), "r"(b1));
}
// pack two floats -> e4m3x2 (lo -> low byte, hi -> high byte)
__device__ __forceinline__ uint16_t pack_e4m3x2(float lo, float hi) {
    uint16_t r;
    asm("cvt.rn.satfinite.e4m3x2.f32 %0, %1, %2;" : "=h"(r) : "f"(hi), "f"(lo));
    return r;
}
__device__ __forceinline__ float2 unpack_e4m3x2(uint16_t v) {
    uint32_t h2;
    asm("cvt.rn.f16x2.e4m3x2 %0, %1;" : "=r"(h2) : "h"(v));
    __half2 hh = *reinterpret_cast<__half2*>(&h2);
    return __half22float2(hh);
}
__device__ __forceinline__ void atomicMaxFloat(float* addr, float v) {
    if (v >= 0.0f) atomicMax((int*)addr, __float_as_int(v));
    else           atomicMin((unsigned int*)addr, __float_as_uint(v));
}

// ---------------- reductions ----------------
__device__ __forceinline__ float warpReduceSum(float v) {
#pragma unroll
    for (int o = 16; o > 0; o >>= 1) v += __shfl_xor_sync(0xffffffffu, v, o);
    return v;
}
__device__ __forceinline__ float warpReduceMax(float v) {
#pragma unroll
    for (int o = 16; o > 0; o >>= 1) v = fmaxf(v, __shfl_xor_sync(0xffffffffu, v, o));
    return v;
}
__device__ __forceinline__ float blockReduceSum(float v) {
    __shared__ float sh[8];
    int lane = threadIdx.x & 31, w = threadIdx.x >> 5;
    v = warpReduceSum(v);
    if (lane == 0) sh[w] = v;
    __syncthreads();
    v = (threadIdx.x < 8) ? sh[threadIdx.x] : 0.0f;
    if (w == 0) v = warpReduceSum(v);
    __syncthreads();
    return v;
}
__device__ __forceinline__ float blockReduceMax(float v) {
    __shared__ float sh[8];
    int lane = threadIdx.x & 31, w = threadIdx.x >> 5;
    v = warpReduceMax(v);
    if (lane == 0) sh[w] = v;
    __syncthreads();
    v = (threadIdx.x < 8) ? sh[threadIdx.x] : -3.0e38f;
    if (w == 0) v = warpReduceMax(v);
    __syncthreads();
    return v;
}

// ---------------- stage 1: per-channel mean of y ----------------
__global__ void ymu_kernel(const float* __restrict__ y) {
    const int c = blockIdx.x;
    const float4* row = reinterpret_cast<const float4*>(y + (size_t)c * HWN);
    float s = 0.0f;
    for (int j = threadIdx.x; j < HWN / 4; j += blockDim.x) {
        float4 v = row[j];
        s += (v.x + v.y) + (v.z + v.w);
    }
    s = blockReduceSum(s);
    if (threadIdx.x == 0) g_ymu[c] = s * (1.0f / HWN);
}

// ---------------- stage 2: center + transpose to bf16 [i][c] (no scale) ----------------
__global__ void transpose_kernel(const float* __restrict__ v, __nv_bfloat16* __restrict__ o) {
    __shared__ float tile[32][33];
    __shared__ float mu[32];
    const int i0 = blockIdx.x * 32;
    const int c0 = blockIdx.y * 32;
    const int tx = threadIdx.x, ty = threadIdx.y;   // (32, 8)
    if (ty == 0) mu[tx] = g_ymu[c0 + tx];
    __syncthreads();
#pragma unroll
    for (int r = 0; r < 4; r++) {
        int cl = ty + 8 * r;
        tile[cl][tx] = v[(size_t)(c0 + cl) * HWN + i0 + tx] - mu[cl];
    }
    __syncthreads();
#pragma unroll
    for (int r = 0; r < 4; r++) {
        int il = ty + 8 * r;
        o[(size_t)(i0 + il) * CC + c0 + tx] = __float2bfloat16(tile[tx][il]);
    }
}

// ---------------- stage 3: per-row inverse norm from bf16 rows (+rowmax init) ----------------
__global__ void rownorm_kernel(const __nv_bfloat16* __restrict__ b, float* __restrict__ sinv) {
    const int row  = blockIdx.x * 8 + (threadIdx.x >> 5);
    const int lane = threadIdx.x & 31;
    const uint4* r = reinterpret_cast<const uint4*>(b + (size_t)row * CC);
    float s = 0.0f;
#pragma unroll
    for (int q = 0; q < 2; q++) {
        uint4 u = r[lane + q * 32];
        const __nv_bfloat162* p = reinterpret_cast<const __nv_bfloat162*>(&u);
#pragma unroll
        for (int t = 0; t < 4; t++) {
            float2 f = __bfloat1622float2(p[t]);
            s = fmaf(f.x, f.x, s);
            s = fmaf(f.y, f.y, s);
        }
    }
    s = warpReduceSum(s);
    if (lane == 0) {
        sinv[row] = 1.0f / fmaxf(sqrtf(s), 1e-12f);
        g_rowmax[row] = -3.0e38f;
    }
}

// ---------------- stage 4: bf16 warp-MMA GEMM, A stored as e4m3 ----------------
// CTA tile 128x128, 8 warps 2(m) x 4(n), warp tile 64x32, BK=32,
// 4-stage cp.async pipeline (distance 3, ONE sync per chunk), rows padded 80 B,
// 2 CTAs/SM. Epilogue stages fp8 tile through SMEM for coalesced 128B stores.
#define BM 128
#define BN 128
#define BK 32
#define ROWB 80          // 32 bf16 = 64B data + 16B pad
#define NKC (CC / BK)    // 16 k-chunks
#define STG 4
#define ABYTES (BM * ROWB)
#define BBYTES (BN * ROWB)
#define TILE_PITCH 144   // fp8 epilogue tile row pitch (16B-aligned, bank-staggered)
#define GEMM_SMEM (STG * (ABYTES + BBYTES) + 512)

__global__ void __launch_bounds__(256, 2) gemm_mma(const __nv_bfloat16* __restrict__ X,
                                                   const __nv_bfloat16* __restrict__ Y,
                                                   uint8_t* __restrict__ A) {
    extern __shared__ __align__(16) char dyn[];
    char* sAp = dyn;
    char* sBp = dyn + STG * ABYTES;
    float* sRM = reinterpret_cast<float*>(dyn + STG * (ABYTES + BBYTES));

    const int tid  = threadIdx.x;
    const int wid  = tid >> 5;
    const int lane = tid & 31;
    const int wm   = wid & 1;        // 0..1 -> 64-row slab
    const int wn   = wid >> 1;       // 0..3 -> 32-col slab
    const int i0   = blockIdx.y * BM;
    const int j0   = blockIdx.x * BN;

    if (tid < BM) sRM[tid] = -3.0e38f;

    const uint32_t aBase = smem_to_u32(sAp);
    const uint32_t bBase = smem_to_u32(sBp);

    const int r0 = tid >> 2,         s0 = tid & 3;
    const int r1 = (tid + 256) >> 2, s1 = (tid + 256) & 3;
    const __nv_bfloat16* Xg = X + (size_t)i0 * CC;
    const __nv_bfloat16* Yg = Y + (size_t)j0 * CC;

    auto issue_chunk = [&](int kc, int buf) {
        const uint32_t da = aBase + buf * ABYTES;
        const uint32_t db = bBase + buf * BBYTES;
        const int ko = kc * BK;
        cp_async16(da + r0 * ROWB + s0 * 16, Xg + (size_t)r0 * CC + ko + s0 * 8);
        cp_async16(da + r1 * ROWB + s1 * 16, Xg + (size_t)r1 * CC + ko + s1 * 8);
        cp_async16(db + r0 * ROWB + s0 * 16, Yg + (size_t)r0 * CC + ko + s0 * 8);
        cp_async16(db + r1 * ROWB + s1 * 16, Yg + (size_t)r1 * CC + ko + s1 * 8);
        cp_commit();
    };

    float acc[4][4][4];
#pragma unroll
    for (int mt = 0; mt < 4; mt++)
#pragma unroll
        for (int nt = 0; nt < 4; nt++)
#pragma unroll
            for (int q = 0; q < 4; q++) acc[mt][nt][q] = 0.0f;

    issue_chunk(0, 0);
    issue_chunk(1, 1);
    issue_chunk(2, 2);

    const int aRow = wm * 64 + (lane & 15);
    const uint32_t aColHalf = ((lane >> 4) & 1) * 16;
    const int bRow = wn * 32 + (lane & 7) + ((lane >> 4) & 1) * 8;
    const uint32_t bColHalf = ((lane >> 3) & 1) * 16;

    for (int kc = 0; kc < NKC; kc++) {
        if (kc <= NKC - 3)      cp_wait<2>();
        else if (kc == NKC - 2) cp_wait<1>();
        else                    cp_wait<0>();
        __syncthreads();   // single barrier per chunk (see distance-3 safety note)

        const int buf = kc & 3;
        const uint32_t ab = aBase + buf * ABYTES;
        const uint32_t bb = bBase + buf * BBYTES;
#pragma unroll
        for (int ks = 0; ks < 2; ks++) {
            uint32_t afr[4][4];
#pragma unroll
            for (int mt = 0; mt < 4; mt++)
                ldmatrix_x4(afr[mt], ab + (uint32_t)(aRow + mt * 16) * ROWB + ks * 32 + aColHalf);
            uint32_t bfr[2][4];
#pragma unroll
            for (int pr = 0; pr < 2; pr++)
                ldmatrix_x4(bfr[pr], bb + (uint32_t)(bRow + pr * 16) * ROWB + ks * 32 + bColHalf);
#pragma unroll
            for (int mt = 0; mt < 4; mt++)
#pragma unroll
                for (int nt = 0; nt < 4; nt++)
                    mma_16816(acc[mt][nt], afr[mt],
                              bfr[nt >> 1][(nt & 1) * 2], bfr[nt >> 1][(nt & 1) * 2 + 1]);
        }
        if (kc + 3 < NKC) issue_chunk(kc + 3, (kc + 3) & 3);
    }

    // ---------------- epilogue: scale, rowmax, fp8 tile in SMEM, coalesced store ----
    __syncthreads();    // pipeline buffers now reusable as the fp8 tile
    char* tile = dyn;   // 128 rows x TILE_PITCH bytes (18,432 B < 3*ABYTES)

    const int colb = wn * 32 + 2 * (lane & 3);
    float sy0[4], sy1[4];
#pragma unroll
    for (int nt = 0; nt < 4; nt++) {
        sy0[nt] = g_sinvy[j0 + colb + nt * 8];
        sy1[nt] = g_sinvy[j0 + colb + nt * 8 + 1];
    }
#pragma unroll
    for (int mt = 0; mt < 4; mt++) {
        const int rlo = wm * 64 + mt * 16 + (lane >> 2);
        const float sxlo = g_sinvx[i0 + rlo];
        const float sxhi = g_sinvx[i0 + rlo + 8];
        float maxlo = -3.0e38f, maxhi = -3.0e38f;
#pragma unroll
        for (int nt = 0; nt < 4; nt++) {
            float c0 = acc[mt][nt][0] * sxlo * sy0[nt];
            float c1 = acc[mt][nt][1] * sxlo * sy1[nt];
            float c2 = acc[mt][nt][2] * sxhi * sy0[nt];
            float c3 = acc[mt][nt][3] * sxhi * sy1[nt];
            maxlo = fmaxf(maxlo, fmaxf(c0, c1));
            maxhi = fmaxf(maxhi, fmaxf(c2, c3));
            *reinterpret_cast<uint16_t*>(tile + rlo * TILE_PITCH + colb + nt * 8)
                = pack_e4m3x2(c0, c1);
            *reinterpret_cast<uint16_t*>(tile + (rlo + 8) * TILE_PITCH + colb + nt * 8)
                = pack_e4m3x2(c2, c3);
        }
        maxlo = fmaxf(maxlo, __shfl_xor_sync(0xffffffffu, maxlo, 1));
        maxlo = fmaxf(maxlo, __shfl_xor_sync(0xffffffffu, maxlo, 2));
        maxhi = fmaxf(maxhi, __shfl_xor_sync(0xffffffffu, maxhi, 1));
        maxhi = fmaxf(maxhi, __shfl_xor_sync(0xffffffffu, maxhi, 2));
        if ((lane & 3) == 0) {
            atomicMaxFloat(&sRM[rlo],     maxlo);
            atomicMaxFloat(&sRM[rlo + 8], maxhi);
        }
    }
    __syncthreads();

    // coalesced copy-out: each 128-byte A-row written as 8 x uint4
#pragma unroll
    for (int idx = tid; idx < BM * 8; idx += 256) {
        const int row = idx >> 3, seg = idx & 7;
        uint4 v = *reinterpret_cast<uint4*>(tile + row * TILE_PITCH + seg * 16);
        *reinterpret_cast<uint4*>(A + (size_t)(i0 + row) * HWN + j0 + seg * 16) = v;
    }
    if (tid < BM) atomicMaxFloat(&g_rowmax[i0 + tid], sRM[tid]);
}

// ---------------- stage 5: per-row exp pass over fp8 A -> k[i] ----------------
// cx_sp == I (spatial branch collapses to identity in fp32; see R2 analysis)
__global__ void cx_row_kernel(const uint8_t* __restrict__ A) {
    const int row = blockIdx.x;
    const float beta  = 2.0f / (1.0f - g_rowmax[row] + EPS5);
    const float alpha = 2.0f - beta;
    const uint4* Ar = reinterpret_cast<const uint4*>(A + (size_t)row * HWN);
    float s = 0.0f, m = 0.0f;
    for (int q = threadIdx.x; q < HWN / 16; q += blockDim.x) {
        uint4 u = Ar[q];
        const uint16_t* p = reinterpret_cast<const uint16_t*>(&u);
#pragma unroll
        for (int t = 0; t < 8; t++) {
            float2 f = unpack_e4m3x2(p[t]);
            float w0 = __expf(fmaf(beta, f.x, alpha));
            float w1 = __expf(fmaf(beta, f.y, alpha));
            s += w0 + w1;
            m = fmaxf(m, fmaxf(w0, w1));
        }
    }
    s = blockReduceSum(s);
    m = blockReduceMax(m);
    if (threadIdx.x == 0) {
        uint16_t dv = *reinterpret_cast<const uint16_t*>(A + (size_t)row * HWN + (row & ~1));
        float2 df = unpack_e4m3x2(dv);
        float aii = (row & 1) ? df.y : df.x;
        float wii = __expf(fmaf(beta, aii, alpha));
        float inv_s = 1.0f / s;
        g_k[row] = fmaxf(0.9f * m * inv_s, fmaf(0.9f * wii, inv_s, 0.1f));
    }
}

// ---------------- stage 6: scalar output ----------------
__global__ void final_kernel(float* __restrict__ out) {
    float s = 0.0f;
    for (int i = threadIdx.x; i < HWN; i += blockDim.x) s += g_k[i];
    s = blockReduceSum(s);
    if (threadIdx.x == 0) out[0] = -logf(s * (1.0f / HWN) + EPS5);
}

// ---------------- launch ----------------
extern "C" void kernel_launch(void* const* d_in, const int* in_sizes, int n_in,
                              void* d_out, int out_size) {
    const float* x = (const float*)d_in[0];
    const float* y = (const float*)d_in[1];
    float* out = (float*)d_out;

    __nv_bfloat16 *pxb, *pyb;
    uint8_t* pA8;
    float *psx, *psy;
    cudaGetSymbolAddress((void**)&pxb, g_xb);
    cudaGetSymbolAddress((void**)&pyb, g_yb);
    cudaGetSymbolAddress((void**)&pA8, g_A8);
    cudaGetSymbolAddress((void**)&psx, g_sinvx);
    cudaGetSymbolAddress((void**)&psy, g_sinvy);

    static bool attr_set = false;
    if (!attr_set) {
        cudaFuncSetAttribute(gemm_mma, cudaFuncAttributeMaxDynamicSharedMemorySize, GEMM_SMEM);
        attr_set = true;
    }

    ymu_kernel<<<CC, 256>>>(y);
    transpose_kernel<<<dim3(HWN / 32, CC / 32), dim3(32, 8)>>>(x, pxb);
    transpose_kernel<<<dim3(HWN / 32, CC / 32), dim3(32, 8)>>>(y, pyb);
    rownorm_kernel<<<HWN / 8, 256>>>(pxb, psx);
    rownorm_kernel<<<HWN / 8, 256>>>(pyb, psy);
    gemm_mma<<<dim3(HWN / BN, HWN / BM), 256, GEMM_SMEM>>>(pxb, pyb, pA8);
    cx_row_kernel<<<HWN, 256>>>(pA8);
    final_kernel<<<1, 256>>>(out);
}